// round 6
// baseline (speedup 1.0000x reference)
#include <cuda_runtime.h>

typedef unsigned long long ull;

// ---- f32x2 packed helpers (sm_100+; ptxas won't auto-generate these) ----
__device__ __forceinline__ ull pk2(float lo, float hi) {
    ull r; asm("mov.b64 %0, {%1,%2};" : "=l"(r) : "f"(lo), "f"(hi)); return r;
}
__device__ __forceinline__ ull f2fma(ull a, ull b, ull c) {
    ull d; asm("fma.rn.f32x2 %0, %1, %2, %3;" : "=l"(d) : "l"(a), "l"(b), "l"(c)); return d;
}
__device__ __forceinline__ void unpk2(ull v, float& lo, float& hi) {
    asm("mov.b64 {%0,%1}, %2;" : "=f"(lo), "=f"(hi) : "l"(v));
}

// ---------------------------------------------------------------------------
// Fully fused. Prologue (per block): shuffle-simulate U (16x16), M = Re(U^dag
// Z0 U), sparse-project to 81 multilinear coefficients K, stored DUPLICATED in
// shared for packed-lane consumption. Main: persistent grid-stride over
// 4-pixel strips, two pixels per packed f32x2 lane-pair.
// ---------------------------------------------------------------------------
__global__ void __launch_bounds__(256, 4)
qcl_fused_kernel(const float* __restrict__ x, const float* __restrict__ w,
                 float* __restrict__ out, int nStrips) {
    __shared__ float sUr[16][17];
    __shared__ float sUi[16][17];
    __shared__ float sM[16][17];
    __shared__ float sgc[24], sgs[24];
    // entry e=(t0*3+t1)*3+t2: {K(t3=0) x2, K(t3=1) x2, K(t3=2) x2, pad, pad}
    __shared__ __align__(16) float sKd[27][8];

    const int tid = threadIdx.x;

    // ---- weights' half-angle sincos ----
    if (tid < 24) {
        sgc[tid] = cosf(w[tid] * 0.5f);
        sgs[tid] = sinf(w[tid] * 0.5f);
    }
    __syncthreads();

    // ---- shuffle simulator: thread owns amplitude kk of column col ----
    {
        const int lane = tid & 31;
        const int kk   = lane & 15;
        const int col  = ((tid >> 5) << 1) | (lane >> 4);

        float ar = (kk == col) ? 1.f : 0.f;
        float ai = 0.f;

        auto rot = [&](int m, float g00r, float g00i, float g01r, float g01i,
                              float g10r, float g10i, float g11r, float g11i) {
            float pr = __shfl_xor_sync(0xffffffffu, ar, m);
            float pi = __shfl_xor_sync(0xffffffffu, ai, m);
            bool  b  = (kk & m) != 0;
            float ur = b ? pr : ar, ui = b ? pi : ai;
            float wr = b ? ar : pr, wi = b ? ai : pi;
            float c0r = b ? g10r : g00r, c0i = b ? g10i : g00i;
            float c1r = b ? g11r : g01r, c1i = b ? g11i : g01i;
            ar = c0r * ur - c0i * ui + c1r * wr - c1i * wi;
            ai = c0r * ui + c0i * ur + c1r * wi + c1i * wr;
        };
        auto cnot = [&](int mc, int mt) {
            float pr = __shfl_xor_sync(0xffffffffu, ar, mt);
            float pi = __shfl_xor_sync(0xffffffffu, ai, mt);
            if (kk & mc) { ar = pr; ai = pi; }
        };

        #pragma unroll
        for (int g8 = 0; g8 < 8; g8++) {     // layer*4 + q
            int q = g8 & 3;
            int m = 8 >> q;
            int base = g8 * 3;
            float c, s;
            c = sgc[base + 0]; s = sgs[base + 0];          // RX
            rot(m, c, 0.f, 0.f, -s, 0.f, -s, c, 0.f);
            c = sgc[base + 1]; s = sgs[base + 1];          // RY
            rot(m, c, 0.f, -s, 0.f, s, 0.f, c, 0.f);
            c = sgc[base + 2]; s = sgs[base + 2];          // RZ
            rot(m, c, -s, 0.f, 0.f, 0.f, 0.f, c, s);
            if (q == 3) { cnot(8, 4); cnot(2, 1); cnot(8, 2); cnot(4, 1); }
        }

        sUr[kk][col] = ar;
        sUi[kk][col] = ai;
    }
    __syncthreads();

    // ---- M[i][j] = Re(sum_k z_k conj(U[k][i]) U[k][j]), z_k = (k&8)?-1:+1 ----
    {
        int i = tid >> 4, j = tid & 15;
        float acc = 0.f;
        #pragma unroll
        for (int k = 0; k < 16; k++) {
            float z = (k & 8) ? -1.f : 1.f;
            acc += z * (sUr[k][i] * sUr[k][j] + sUi[k][i] * sUi[k][j]);
        }
        sM[i][j] = acc;
    }
    __syncthreads();

    // ---- sparse projection, duplicated store ----
    // K[t] = (1/16) sum_c (-1)^popc(c & smask) * M[c][c ^ xmask]
    if (tid < 81) {
        int t3 = tid % 3, r = tid / 3;
        int t2 = r % 3;  r /= 3;
        int t1 = r % 3;
        int t0 = r / 3;
        int xmask = ((t0 == 2) << 3) | ((t1 == 2) << 2) | ((t2 == 2) << 1) | (t3 == 2);
        int smask = ((t0 == 1) << 3) | ((t1 == 1) << 2) | ((t2 == 1) << 1) | (t3 == 1);
        float acc = 0.f;
        #pragma unroll
        for (int c = 0; c < 16; c++) {
            float sgn = (__popc(c & smask) & 1) ? -1.f : 1.f;
            acc += sgn * sM[c][c ^ xmask];
        }
        acc *= 0.0625f;
        int e = (t0 * 3 + t1) * 3 + t2;
        sKd[e][2 * t3 + 0] = acc;
        sKd[e][2 * t3 + 1] = acc;
    }
    __syncthreads();

    // ---- packed bilinear contraction for a pixel pair ----
    auto contract = [&](ull C0p, ull S0p, ull C1p, ull S1p,
                        ull C2p, ull S2p, ull C3p, ull S3p) -> ull {
        ull acc_a = 0;
        #pragma unroll
        for (int a = 0; a < 3; a++) {
            ull acc_b = 0;
            #pragma unroll
            for (int b = 0; b < 3; b++) {
                ull tt[3];
                #pragma unroll
                for (int c = 0; c < 3; c++) {
                    const int e = (a * 3 + b) * 3 + c;
                    ulonglong2 k01 = *(const ulonglong2*)&sKd[e][0]; // (k0,k0),(k1,k1)
                    ull        k2  = *(const ull*)&sKd[e][4];        // (k2,k2)
                    tt[c] = f2fma(k01.y, C3p, f2fma(k2, S3p, k01.x));
                }
                ull s = f2fma(tt[1], C2p, f2fma(tt[2], S2p, tt[0]));
                acc_b = (b == 0) ? s : f2fma(s, (b == 1) ? C1p : S1p, acc_b);
            }
            acc_a = (a == 0) ? acc_b : f2fma(acc_b, (a == 1) ? C0p : S0p, acc_a);
        }
        return acc_a;
    };

    // ---- main phase: persistent grid-stride over 4-pixel strips ----
    const int stride = gridDim.x * blockDim.x;
    for (int sid = blockIdx.x * blockDim.x + tid; sid < nStrips; sid += stride) {
        // strips: 32 per row (last covers 3 pixels), 127 rows, 96 planes
        int p    = sid / 4064;            // 127*32
        int rem  = sid - p * 4064;
        int h    = rem >> 5;
        int w0   = (rem & 31) << 2;       // 0..124, 16B-aligned
        bool full = (w0 < 124);

        const float* r0 = x + p * 16384 + h * 128 + w0;
        float4 t4 = *(const float4*)r0;
        float4 b4 = *(const float4*)(r0 + 128);
        float  t5 = full ? __ldg(r0 + 4)   : 0.f;
        float  b5 = full ? __ldg(r0 + 132) : 0.f;

        float Ct[5], St[5], Cb[5], Sb[5];
        __sincosf(t4.x, &St[0], &Ct[0]);  __sincosf(b4.x, &Sb[0], &Cb[0]);
        __sincosf(t4.y, &St[1], &Ct[1]);  __sincosf(b4.y, &Sb[1], &Cb[1]);
        __sincosf(t4.z, &St[2], &Ct[2]);  __sincosf(b4.z, &Sb[2], &Cb[2]);
        __sincosf(t4.w, &St[3], &Ct[3]);  __sincosf(b4.w, &Sb[3], &Cb[3]);
        __sincosf(t5,   &St[4], &Ct[4]);  __sincosf(b5,   &Sb[4], &Cb[4]);

        // pair (pixels 0,1): wires 0=top-left, 1=top-right, 2=bot-left, 3=bot-right
        ull ev01 = contract(pk2(Ct[0], Ct[1]), pk2(St[0], St[1]),
                            pk2(Ct[1], Ct[2]), pk2(St[1], St[2]),
                            pk2(Cb[0], Cb[1]), pk2(Sb[0], Sb[1]),
                            pk2(Cb[1], Cb[2]), pk2(Sb[1], Sb[2]));
        // pair (pixels 2,3)
        ull ev23 = contract(pk2(Ct[2], Ct[3]), pk2(St[2], St[3]),
                            pk2(Ct[3], Ct[4]), pk2(St[3], St[4]),
                            pk2(Cb[2], Cb[3]), pk2(Sb[2], Sb[3]),
                            pk2(Cb[3], Cb[4]), pk2(Sb[3], Sb[4]));

        float* o = out + p * 16129 + h * 127 + w0;   // 4B-aligned only
        float e0, e1, e2, e3;
        unpk2(ev01, e0, e1);
        unpk2(ev23, e2, e3);
        o[0] = e0; o[1] = e1; o[2] = e2;
        if (full) o[3] = e3;
    }
}

extern "C" void kernel_launch(void* const* d_in, const int* in_sizes, int n_in,
                              void* d_out, int out_size) {
    const float* x = (const float*)d_in[0];   // [32,3,128,128]
    const float* w = (const float*)d_in[1];   // [2,4,3]
    float* out = (float*)d_out;               // [32,3,127,127]

    const int nStrips = 96 * 127 * 32;        // 390144
    const int blocks  = 592;                  // one wave: 4 blocks/SM x 148 SMs
    qcl_fused_kernel<<<blocks, 256>>>(x, w, out, nStrips);
}

// round 8
// speedup vs baseline: 4.0692x; 4.0692x over previous
#include <cuda_runtime.h>

// ---------------------------------------------------------------------------
// Fully fused. Prologue (per block, redundant, ~µs): shuffle-simulate the
// 16x16 circuit unitary U from weights, M = Re(U^dag Z0 U), sparse-project to
// 81 multilinear coefficients K[t0,t1,t2,t3] stored as 27 float4 entries
// {k(t3=0), k(t3=1), k(t3=2), 0}. Main: persistent grid-stride over 4-pixel
// strips; per pixel: nested 3x3x3 contraction, 27 LDS.128 + ~82 FMA, ~6 live
// temporaries (no r[] array -> low register pressure, no spills).
//   ev = sum_{t in {1,C,S}^4} K[t] * prod_q e_q(t_q)
// ---------------------------------------------------------------------------
__global__ void __launch_bounds__(256)
qcl_fused_kernel(const float* __restrict__ x, const float* __restrict__ w,
                 float* __restrict__ out, int nStrips) {
    __shared__ float sUr[16][17];
    __shared__ float sUi[16][17];
    __shared__ float sM[16][17];
    __shared__ float sgc[24], sgs[24];
    __shared__ __align__(16) float sKe[27][4];   // {k0,k1,k2,pad} per (t0,t1,t2)

    const int tid = threadIdx.x;

    // ---- weights' half-angle sincos (precise) ----
    if (tid < 24) {
        sgc[tid] = cosf(w[tid] * 0.5f);
        sgs[tid] = sinf(w[tid] * 0.5f);
    }
    __syncthreads();

    // ---- shuffle simulator: thread owns amplitude kk of column col ----
    // 256 threads = 8 warps x (2 columns x 16 amplitudes); masks <16 keep
    // shfl_xor within each 16-lane half (one column each).
    {
        const int lane = tid & 31;
        const int kk   = lane & 15;
        const int col  = ((tid >> 5) << 1) | (lane >> 4);

        float ar = (kk == col) ? 1.f : 0.f;
        float ai = 0.f;

        auto rot = [&](int m, float g00r, float g00i, float g01r, float g01i,
                              float g10r, float g10i, float g11r, float g11i) {
            float pr = __shfl_xor_sync(0xffffffffu, ar, m);
            float pi = __shfl_xor_sync(0xffffffffu, ai, m);
            bool  b  = (kk & m) != 0;
            float ur = b ? pr : ar, ui = b ? pi : ai;   // bit-clear amplitude
            float wr = b ? ar : pr, wi = b ? ai : pi;   // bit-set amplitude
            float c0r = b ? g10r : g00r, c0i = b ? g10i : g00i;
            float c1r = b ? g11r : g01r, c1i = b ? g11i : g01i;
            ar = c0r * ur - c0i * ui + c1r * wr - c1i * wi;
            ai = c0r * ui + c0i * ur + c1r * wi + c1i * wr;
        };
        auto cnot = [&](int mc, int mt) {
            float pr = __shfl_xor_sync(0xffffffffu, ar, mt);
            float pi = __shfl_xor_sync(0xffffffffu, ai, mt);
            if (kk & mc) { ar = pr; ai = pi; }
        };

        #pragma unroll
        for (int g8 = 0; g8 < 8; g8++) {     // layer*4 + q
            int q = g8 & 3;
            int m = 8 >> q;
            int base = g8 * 3;
            float c, s;
            c = sgc[base + 0]; s = sgs[base + 0];          // RX: [[c,-is],[-is,c]]
            rot(m, c, 0.f, 0.f, -s, 0.f, -s, c, 0.f);
            c = sgc[base + 1]; s = sgs[base + 1];          // RY: [[c,-s],[s,c]]
            rot(m, c, 0.f, -s, 0.f, s, 0.f, c, 0.f);
            c = sgc[base + 2]; s = sgs[base + 2];          // RZ: diag(e^-it/2,e^it/2)
            rot(m, c, -s, 0.f, 0.f, 0.f, 0.f, c, s);
            if (q == 3) { cnot(8, 4); cnot(2, 1); cnot(8, 2); cnot(4, 1); }
        }

        sUr[kk][col] = ar;
        sUi[kk][col] = ai;
    }
    __syncthreads();

    // ---- M[i][j] = Re(sum_k z_k conj(U[k][i]) U[k][j]), z_k = (k&8)?-1:+1 ----
    {
        int i = tid >> 4, j = tid & 15;
        float acc = 0.f;
        #pragma unroll
        for (int k = 0; k < 16; k++) {
            float z = (k & 8) ? -1.f : 1.f;
            acc += z * (sUr[k][i] * sUr[k][j] + sUi[k][i] * sUi[k][j]);
        }
        sM[i][j] = acc;
    }
    __syncthreads();

    // ---- sparse projection ----
    // K[t] = (1/16) sum_c (-1)^popc(c & smask) * M[c][c ^ xmask]
    //   xmask bit(3-q) set iff t_q==2 (sin), smask bit(3-q) set iff t_q==1 (cos)
    if (tid < 81) {
        int t3 = tid % 3, r = tid / 3;
        int t2 = r % 3;  r /= 3;
        int t1 = r % 3;
        int t0 = r / 3;
        int xmask = ((t0 == 2) << 3) | ((t1 == 2) << 2) | ((t2 == 2) << 1) | (t3 == 2);
        int smask = ((t0 == 1) << 3) | ((t1 == 1) << 2) | ((t2 == 1) << 1) | (t3 == 1);
        float acc = 0.f;
        #pragma unroll
        for (int c = 0; c < 16; c++) {
            float sgn = (__popc(c & smask) & 1) ? -1.f : 1.f;
            acc += sgn * sM[c][c ^ xmask];
        }
        sKe[(t0 * 3 + t1) * 3 + t2][t3] = acc * 0.0625f;
    }
    if (tid >= 81 && tid < 108) sKe[tid - 81][3] = 0.f;   // pad lanes
    __syncthreads();

    const float4* sKe4 = (const float4*)sKe;

    // ---- nested scalar contraction, minimal live state ----
    auto contract = [&](float C0, float S0, float C1, float S1,
                        float C2, float S2, float C3, float S3) -> float {
        float acc_a = 0.f;
        #pragma unroll
        for (int a = 0; a < 3; a++) {
            float acc_b = 0.f;
            #pragma unroll
            for (int b = 0; b < 3; b++) {
                float4 k0 = sKe4[(a * 3 + b) * 3 + 0];
                float4 k1 = sKe4[(a * 3 + b) * 3 + 1];
                float4 k2 = sKe4[(a * 3 + b) * 3 + 2];
                float t0v = fmaf(k0.y, C3, fmaf(k0.z, S3, k0.x));
                float t1v = fmaf(k1.y, C3, fmaf(k1.z, S3, k1.x));
                float t2v = fmaf(k2.y, C3, fmaf(k2.z, S3, k2.x));
                float s = fmaf(t1v, C2, fmaf(t2v, S2, t0v));
                acc_b = (b == 0) ? s : fmaf(s, (b == 1) ? C1 : S1, acc_b);
            }
            acc_a = (a == 0) ? acc_b : fmaf(acc_b, (a == 1) ? C0 : S0, acc_a);
        }
        return acc_a;
    };

    // ---- main phase: persistent grid-stride over 4-pixel strips ----
    const int stride = gridDim.x * blockDim.x;
    for (int sid = blockIdx.x * blockDim.x + tid; sid < nStrips; sid += stride) {
        // strips: 32 per row (last covers 3 pixels), 127 rows, 96 planes
        int p    = sid / 4064;            // 127*32
        int rem  = sid - p * 4064;
        int h    = rem >> 5;
        int w0   = (rem & 31) << 2;       // 0..124, 16B-aligned
        bool full = (w0 < 124);

        const float* r0 = x + p * 16384 + h * 128 + w0;
        float4 t4 = *(const float4*)r0;
        float4 b4 = *(const float4*)(r0 + 128);
        float  t5 = full ? __ldg(r0 + 4)   : 0.f;
        float  b5 = full ? __ldg(r0 + 132) : 0.f;

        float Ct[5], St[5], Cb[5], Sb[5];
        __sincosf(t4.x, &St[0], &Ct[0]);  __sincosf(b4.x, &Sb[0], &Cb[0]);
        __sincosf(t4.y, &St[1], &Ct[1]);  __sincosf(b4.y, &Sb[1], &Cb[1]);
        __sincosf(t4.z, &St[2], &Ct[2]);  __sincosf(b4.z, &Sb[2], &Cb[2]);
        __sincosf(t4.w, &St[3], &Ct[3]);  __sincosf(b4.w, &Sb[3], &Cb[3]);
        __sincosf(t5,   &St[4], &Ct[4]);  __sincosf(b5,   &Sb[4], &Cb[4]);

        float* o = out + p * 16129 + h * 127 + w0;

        // wires: 0=top-left, 1=top-right, 2=bottom-left, 3=bottom-right
        o[0] = contract(Ct[0], St[0], Ct[1], St[1], Cb[0], Sb[0], Cb[1], Sb[1]);
        o[1] = contract(Ct[1], St[1], Ct[2], St[2], Cb[1], Sb[1], Cb[2], Sb[2]);
        o[2] = contract(Ct[2], St[2], Ct[3], St[3], Cb[2], Sb[2], Cb[3], Sb[3]);
        float e3 = contract(Ct[3], St[3], Ct[4], St[4], Cb[3], Sb[3], Cb[4], Sb[4]);
        if (full) o[3] = e3;
    }
}

extern "C" void kernel_launch(void* const* d_in, const int* in_sizes, int n_in,
                              void* d_out, int out_size) {
    const float* x = (const float*)d_in[0];   // [32,3,128,128]
    const float* w = (const float*)d_in[1];   // [2,4,3]
    float* out = (float*)d_out;               // [32,3,127,127]

    const int nStrips = 96 * 127 * 32;        // 390144
    const int blocks  = 592;                  // persistent, grid-stride
    qcl_fused_kernel<<<blocks, 256>>>(x, w, out, nStrips);
}

// round 9
// speedup vs baseline: 4.1248x; 1.0136x over previous
#include <cuda_runtime.h>

typedef unsigned long long ull;

// ---- f32x2 packed helpers (sm_100+; ptxas won't auto-generate) ----
__device__ __forceinline__ ull pk2(float lo, float hi) {
    ull r; asm("mov.b64 %0, {%1,%2};" : "=l"(r) : "f"(lo), "f"(hi)); return r;
}
__device__ __forceinline__ ull f2fma(ull a, ull b, ull c) {
    ull d; asm("fma.rn.f32x2 %0, %1, %2, %3;" : "=l"(d) : "l"(a), "l"(b), "l"(c)); return d;
}
__device__ __forceinline__ void unpk2(ull v, float& lo, float& hi) {
    asm("mov.b64 {%0,%1}, %2;" : "=f"(lo), "=f"(hi) : "l"(v));
}

// ---------------------------------------------------------------------------
// Fully fused. Prologue (per block): shuffle-simulate U (16x16), M = Re(U^dag
// Z0 U), sparse-project to 81 multilinear K coefficients, stored DUPLICATED
// per lane-pair in shared. Main: persistent grid-stride over 4-pixel strips;
// both pixel PAIRS share each K load (54 LDS + ~166 packed FMA per strip).
// NO min-blocks occupancy cap: packed ull operands need free registers
// (round-6 regression was the 64-reg cap forcing spills).
// ---------------------------------------------------------------------------
__global__ void __launch_bounds__(256)
qcl_fused_kernel(const float* __restrict__ x, const float* __restrict__ w,
                 float* __restrict__ out, int nStrips) {
    __shared__ float sUr[16][17];
    __shared__ float sUi[16][17];
    __shared__ float sM[16][17];
    __shared__ float sgc[24], sgs[24];
    // entry e=(t0*3+t1)*3+t2: {k0,k0, k1,k1, k2,k2, pad,pad}  (32B row)
    __shared__ __align__(16) float sKd[27][8];

    const int tid = threadIdx.x;

    // ---- weights' half-angle sincos (precise) ----
    if (tid < 24) {
        sgc[tid] = cosf(w[tid] * 0.5f);
        sgs[tid] = sinf(w[tid] * 0.5f);
    }
    __syncthreads();

    // ---- shuffle simulator: thread owns amplitude kk of column col ----
    {
        const int lane = tid & 31;
        const int kk   = lane & 15;
        const int col  = ((tid >> 5) << 1) | (lane >> 4);

        float ar = (kk == col) ? 1.f : 0.f;
        float ai = 0.f;

        auto rot = [&](int m, float g00r, float g00i, float g01r, float g01i,
                              float g10r, float g10i, float g11r, float g11i) {
            float pr = __shfl_xor_sync(0xffffffffu, ar, m);
            float pi = __shfl_xor_sync(0xffffffffu, ai, m);
            bool  b  = (kk & m) != 0;
            float ur = b ? pr : ar, ui = b ? pi : ai;
            float wr = b ? ar : pr, wi = b ? ai : pi;
            float c0r = b ? g10r : g00r, c0i = b ? g10i : g00i;
            float c1r = b ? g11r : g01r, c1i = b ? g11i : g01i;
            ar = c0r * ur - c0i * ui + c1r * wr - c1i * wi;
            ai = c0r * ui + c0i * ur + c1r * wi + c1i * wr;
        };
        auto cnot = [&](int mc, int mt) {
            float pr = __shfl_xor_sync(0xffffffffu, ar, mt);
            float pi = __shfl_xor_sync(0xffffffffu, ai, mt);
            if (kk & mc) { ar = pr; ai = pi; }
        };

        #pragma unroll
        for (int g8 = 0; g8 < 8; g8++) {     // layer*4 + q
            int q = g8 & 3;
            int m = 8 >> q;
            int base = g8 * 3;
            float c, s;
            c = sgc[base + 0]; s = sgs[base + 0];          // RX
            rot(m, c, 0.f, 0.f, -s, 0.f, -s, c, 0.f);
            c = sgc[base + 1]; s = sgs[base + 1];          // RY
            rot(m, c, 0.f, -s, 0.f, s, 0.f, c, 0.f);
            c = sgc[base + 2]; s = sgs[base + 2];          // RZ
            rot(m, c, -s, 0.f, 0.f, 0.f, 0.f, c, s);
            if (q == 3) { cnot(8, 4); cnot(2, 1); cnot(8, 2); cnot(4, 1); }
        }

        sUr[kk][col] = ar;
        sUi[kk][col] = ai;
    }
    __syncthreads();

    // ---- M[i][j] = Re(sum_k z_k conj(U[k][i]) U[k][j]), z_k = (k&8)?-1:+1 ----
    {
        int i = tid >> 4, j = tid & 15;
        float acc = 0.f;
        #pragma unroll
        for (int k = 0; k < 16; k++) {
            float z = (k & 8) ? -1.f : 1.f;
            acc += z * (sUr[k][i] * sUr[k][j] + sUi[k][i] * sUi[k][j]);
        }
        sM[i][j] = acc;
    }
    __syncthreads();

    // ---- sparse projection, duplicated store ----
    // K[t] = (1/16) sum_c (-1)^popc(c & smask) * M[c][c ^ xmask]
    if (tid < 81) {
        int t3 = tid % 3, r = tid / 3;
        int t2 = r % 3;  r /= 3;
        int t1 = r % 3;
        int t0 = r / 3;
        int xmask = ((t0 == 2) << 3) | ((t1 == 2) << 2) | ((t2 == 2) << 1) | (t3 == 2);
        int smask = ((t0 == 1) << 3) | ((t1 == 1) << 2) | ((t2 == 1) << 1) | (t3 == 1);
        float acc = 0.f;
        #pragma unroll
        for (int c = 0; c < 16; c++) {
            float sgn = (__popc(c & smask) & 1) ? -1.f : 1.f;
            acc += sgn * sM[c][c ^ xmask];
        }
        acc *= 0.0625f;
        int e = (t0 * 3 + t1) * 3 + t2;
        sKd[e][2 * t3 + 0] = acc;
        sKd[e][2 * t3 + 1] = acc;
    }
    if (tid >= 81 && tid < 108) {               // pad slots
        sKd[tid - 81][6] = 0.f;
        sKd[tid - 81][7] = 0.f;
    }
    __syncthreads();

    // ---- main phase: persistent grid-stride over 4-pixel strips ----
    const int stride = gridDim.x * blockDim.x;
    for (int sid = blockIdx.x * blockDim.x + tid; sid < nStrips; sid += stride) {
        // strips: 32 per row (last covers 3 pixels), 127 rows, 96 planes
        int p    = sid / 4064;            // 127*32
        int rem  = sid - p * 4064;
        int h    = rem >> 5;
        int w0   = (rem & 31) << 2;       // 0..124, 16B-aligned
        bool full = (w0 < 124);

        const float* r0 = x + p * 16384 + h * 128 + w0;
        float4 t4 = *(const float4*)r0;
        float4 b4 = *(const float4*)(r0 + 128);
        float  t5 = full ? __ldg(r0 + 4)   : 0.f;
        float  b5 = full ? __ldg(r0 + 132) : 0.f;

        float Ct0,St0,Ct1,St1,Ct2,St2,Ct3,St3,Ct4,St4;
        float Cb0,Sb0,Cb1,Sb1,Cb2,Sb2,Cb3,Sb3,Cb4,Sb4;
        __sincosf(t4.x, &St0, &Ct0);  __sincosf(b4.x, &Sb0, &Cb0);
        __sincosf(t4.y, &St1, &Ct1);  __sincosf(b4.y, &Sb1, &Cb1);
        __sincosf(t4.z, &St2, &Ct2);  __sincosf(b4.z, &Sb2, &Cb2);
        __sincosf(t4.w, &St3, &Ct3);  __sincosf(b4.w, &Sb3, &Cb3);
        __sincosf(t5,   &St4, &Ct4);  __sincosf(b5,   &Sb4, &Cb4);

        // packed per-pair angle vectors: pair A = pixels(0,1), pair B = pixels(2,3)
        // wires: 0=top-left, 1=top-right, 2=bottom-left, 3=bottom-right
        ull C0A = pk2(Ct0, Ct1), C0B = pk2(Ct2, Ct3);
        ull S0A = pk2(St0, St1), S0B = pk2(St2, St3);
        ull C1A = pk2(Ct1, Ct2), C1B = pk2(Ct3, Ct4);
        ull S1A = pk2(St1, St2), S1B = pk2(St3, St4);
        ull C2A = pk2(Cb0, Cb1), C2B = pk2(Cb2, Cb3);
        ull S2A = pk2(Sb0, Sb1), S2B = pk2(Sb2, Sb3);
        ull C3A = pk2(Cb1, Cb2), C3B = pk2(Cb3, Cb4);
        ull S3A = pk2(Sb1, Sb2), S3B = pk2(Sb3, Sb4);

        ull accA_A = 0, accA_B = 0;
        #pragma unroll
        for (int a = 0; a < 3; a++) {
            ull accB_A = 0, accB_B = 0;
            #pragma unroll
            for (int b = 0; b < 3; b++) {
                ull ttA[3], ttB[3];
                #pragma unroll
                for (int c = 0; c < 3; c++) {
                    const int e = (a * 3 + b) * 3 + c;
                    ulonglong2 k01 = *(const ulonglong2*)&sKd[e][0]; // (k0,k0),(k1,k1)
                    ull        k2  = *(const ull*)&sKd[e][4];        // (k2,k2)
                    ttA[c] = f2fma(k01.y, C3A, f2fma(k2, S3A, k01.x));
                    ttB[c] = f2fma(k01.y, C3B, f2fma(k2, S3B, k01.x));
                }
                ull sA = f2fma(ttA[1], C2A, f2fma(ttA[2], S2A, ttA[0]));
                ull sB = f2fma(ttB[1], C2B, f2fma(ttB[2], S2B, ttB[0]));
                accB_A = (b == 0) ? sA : f2fma(sA, (b == 1) ? C1A : S1A, accB_A);
                accB_B = (b == 0) ? sB : f2fma(sB, (b == 1) ? C1B : S1B, accB_B);
            }
            accA_A = (a == 0) ? accB_A : f2fma(accB_A, (a == 1) ? C0A : S0A, accA_A);
            accA_B = (a == 0) ? accB_B : f2fma(accB_B, (a == 1) ? C0B : S0B, accA_B);
        }

        float* o = out + p * 16129 + h * 127 + w0;   // 4B-aligned only
        float e0, e1, e2, e3;
        unpk2(accA_A, e0, e1);
        unpk2(accA_B, e2, e3);
        o[0] = e0; o[1] = e1; o[2] = e2;
        if (full) o[3] = e3;
    }
}

extern "C" void kernel_launch(void* const* d_in, const int* in_sizes, int n_in,
                              void* d_out, int out_size) {
    const float* x = (const float*)d_in[0];   // [32,3,128,128]
    const float* w = (const float*)d_in[1];   // [2,4,3]
    float* out = (float*)d_out;               // [32,3,127,127]

    const int nStrips = 96 * 127 * 32;        // 390144
    const int blocks  = 444;                  // persistent: single wave even at 3 blocks/SM
    qcl_fused_kernel<<<blocks, 256>>>(x, w, out, nStrips);
}